// round 6
// baseline (speedup 1.0000x reference)
#include <cuda_runtime.h>

#define TILE 128
#define NT_MAX 64
#define MAX_BLOCKS (NT_MAX * (NT_MAX + 1) / 2)   // 2080 for N=8192

// Per-block partial sums + completion counter (no allocations, deterministic).
__device__ double g_partials[MAX_BLOCKS];
__device__ int    g_count = 0;

typedef unsigned long long u64;

// ---------------- packed f32x2 helpers (Blackwell FFMA2 path) ----------------
static __device__ __forceinline__ u64 pack2(float lo, float hi) {
    u64 r; asm("mov.b64 %0, {%1, %2};" : "=l"(r) : "f"(lo), "f"(hi)); return r;
}
static __device__ __forceinline__ float2 unpack2(u64 v) {
    float lo, hi; asm("mov.b64 {%0, %1}, %2;" : "=f"(lo), "=f"(hi) : "l"(v));
    return make_float2(lo, hi);
}
static __device__ __forceinline__ u64 bcast2(float c) { return pack2(c, c); }
static __device__ __forceinline__ u64 add2(u64 a, u64 b) {
    u64 r; asm("add.rn.f32x2 %0, %1, %2;" : "=l"(r) : "l"(a), "l"(b)); return r;
}
static __device__ __forceinline__ u64 mul2(u64 a, u64 b) {
    u64 r; asm("mul.rn.f32x2 %0, %1, %2;" : "=l"(r) : "l"(a), "l"(b)); return r;
}
static __device__ __forceinline__ u64 fma2(u64 a, u64 b, u64 c) {
    u64 r; asm("fma.rn.f32x2 %0, %1, %2, %3;" : "=l"(r) : "l"(a), "l"(b), "l"(c)); return r;
}
static __device__ __forceinline__ u64 ex2_2(u64 x) {   // exp2 of both halves (2 MUFU)
    u64 r;
    asm("{\n\t.reg .f32 a, b;\n\t"
        "mov.b64 {a, b}, %1;\n\t"
        "ex2.approx.f32 a, a;\n\t"
        "ex2.approx.f32 b, b;\n\t"
        "mov.b64 %0, {a, b};\n\t}" : "=l"(r) : "l"(x));
    return r;
}
static __device__ __forceinline__ u64 rcp2(u64 x) {    // rcp of both halves (2 MUFU)
    u64 r;
    asm("{\n\t.reg .f32 a, b;\n\t"
        "mov.b64 {a, b}, %1;\n\t"
        "rcp.approx.f32 a, a;\n\t"
        "rcp.approx.f32 b, b;\n\t"
        "mov.b64 %0, {a, b};\n\t}" : "=l"(r) : "l"(x));
    return r;
}
static __device__ __forceinline__ u64 max0_2(u64 x) {  // max(v,0) per half (2 FMNMX, alu)
    u64 r;
    asm("{\n\t.reg .f32 a, b;\n\t"
        "mov.b64 {a, b}, %1;\n\t"
        "max.f32 a, a, 0f00000000;\n\t"
        "max.f32 b, b, 0f00000000;\n\t"
        "mov.b64 %0, {a, b};\n\t}" : "=l"(r) : "l"(x));
    return r;
}

// degree-5 minimax (Chebyshev-derived) for log1p(e), e in [0,1]; |err| ~2e-5
#define P_B0  6.6e-7f
#define P_B1  0.99923558f
#define P_B2 -0.49023112f
#define P_B3  0.28527296f
#define P_B4 -0.13158144f
#define P_B5  0.03044864f

#define LOG2E     1.44269504088896340f
#define F32_INF   __int_as_float(0x7f800000)

__global__ void __launch_bounds__(TILE)
wrnl_kernel(const float* __restrict__ logits,
            const int* __restrict__ rankings,   // JAX x64 disabled -> int32
            float* __restrict__ out,
            int n, int nt, int nblocks) {
    const int t = threadIdx.x;

    // ---- decode triangular block index k -> (ti, tj), ti <= tj ----
    const int k = blockIdx.x;
    float bb = 2.0f * (float)nt + 1.0f;
    int ti = (int)((bb - sqrtf(bb * bb - 8.0f * (float)k)) * 0.5f);
    while (ti > 0 && k < ti * nt - (ti * (ti - 1)) / 2) --ti;
    while (k >= (ti + 1) * nt - ((ti + 1) * ti) / 2) ++ti;
    const int tj = ti + (k - (ti * nt - (ti * (ti - 1)) / 2));

    // j-tile data, packed as adjacent pairs so LDS.64 lands in register pairs
    __shared__ float2 sL[TILE / 2];   // {l_{2b}, l_{2b+1}}
    __shared__ float2 sR[TILE / 2];   // {r_{2b}, r_{2b+1}}

    const int gi = ti * TILE + t;
    const int gj = tj * TILE + t;

    float li, ri;
    if (gi < n) { li = logits[gi]; ri = (float)rankings[gi]; }
    else        { li = 0.0f;       ri = 3.0e9f; }            // never active
    if (gj < n) {
        ((float*)sL)[t] = logits[gj];
        ((float*)sR)[t] = (float)rankings[gj];
    } else {
        ((float*)sL)[t] = 0.0f;
        ((float*)sR)[t] = -1.0f;                             // rj=-1 -> inactive
    }
    __syncthreads();

    // packed loop constants
    const u64 NLI2  = bcast2(-li);
    const u64 L2E2  = bcast2(LOG2E);
    const u64 B0 = bcast2(P_B0), B1 = bcast2(P_B1), B2 = bcast2(P_B2);
    const u64 B3 = bcast2(P_B3), B4 = bcast2(P_B4), B5 = bcast2(P_B5);
    const u64 SIGN2 = 0x8000000080000000ULL;

    u64 ACC = 0ULL;   // packed {0.0f, 0.0f}

    if (ti != tj) {
        // off-diagonal: i<j holds globally; only the rank test gates a pair
        #pragma unroll 8
        for (int b = 0; b < TILE / 2; ++b) {
            float2 lj = sL[b];                       // LDS.64 broadcast
            float2 rj = sR[b];                       // LDS.64 broadcast
            u64 LJ = pack2(lj.x, lj.y);
            u64 D  = add2(LJ, NLI2);                 // d = lj - li   (packed)
            u64 X  = mul2(D, L2E2) | SIGN2;          // -|d|*log2e    (packed mul + LOP)
            u64 E  = ex2_2(X);                       // exp(-|d|)     (2 MUFU)
            u64 P  = fma2(B5, E, B4);                // log1p(e) poly (5 packed FMA)
            P = fma2(P, E, B3);
            P = fma2(P, E, B2);
            P = fma2(P, E, B1);
            P = fma2(P, E, B0);
            u64 SP = add2(P, max0_2(D));             // softplus
            float rs0 = (ri < rj.x) ? (ri + rj.x) : F32_INF;   // rcp(inf)=0 masks
            float rs1 = (ri < rj.y) ? (ri + rj.y) : F32_INF;
            u64 W  = rcp2(pack2(rs0, rs1));          // 2 MUFU
            ACC = fma2(SP, W, ACC);
        }
    } else {
        // diagonal tile: additionally require t < j  (j = 2b, 2b+1)
        #pragma unroll 8
        for (int b = 0; b < TILE / 2; ++b) {
            float2 lj = sL[b];
            float2 rj = sR[b];
            u64 LJ = pack2(lj.x, lj.y);
            u64 D  = add2(LJ, NLI2);
            u64 X  = mul2(D, L2E2) | SIGN2;
            u64 E  = ex2_2(X);
            u64 P  = fma2(B5, E, B4);
            P = fma2(P, E, B3);
            P = fma2(P, E, B2);
            P = fma2(P, E, B1);
            P = fma2(P, E, B0);
            u64 SP = add2(P, max0_2(D));
            int jj = 2 * b;
            float rs0 = ((ri < rj.x) && (t < jj))     ? (ri + rj.x) : F32_INF;
            float rs1 = ((ri < rj.y) && (t < jj + 1)) ? (ri + rj.y) : F32_INF;
            u64 W  = rcp2(pack2(rs0, rs1));
            ACC = fma2(SP, W, ACC);
        }
    }

    // ---- block reduction to one double partial ----
    float2 av = unpack2(ACC);
    float acc = av.x + av.y;
    #pragma unroll
    for (int off = 16; off > 0; off >>= 1)
        acc += __shfl_down_sync(0xffffffffu, acc, off);

    __shared__ float warpSum[4];
    __shared__ bool  isLast;
    if ((t & 31) == 0) warpSum[t >> 5] = acc;
    __syncthreads();
    if (t == 0) {
        double s = (double)warpSum[0] + (double)warpSum[1]
                 + (double)warpSum[2] + (double)warpSum[3];
        g_partials[k] = s;
        __threadfence();
        int old = atomicAdd(&g_count, 1);
        isLast = (old == nblocks - 1);
    }
    __syncthreads();
    if (!isLast) return;

    // ---- last block: deterministic final reduction ----
    __threadfence();
    double a = 0.0;
    for (int i = t; i < nblocks; i += TILE) a += g_partials[i];
    #pragma unroll
    for (int off = 16; off > 0; off >>= 1)
        a += __shfl_down_sync(0xffffffffu, a, off);

    __shared__ double ws2[4];
    if ((t & 31) == 0) ws2[t >> 5] = a;
    __syncthreads();
    if (t == 0) {
        double s = ws2[0] + ws2[1] + ws2[2] + ws2[3];
        out[0] = (float)(s / (double)n);
        g_count = 0;                      // reset for next graph replay
    }
}

extern "C" void kernel_launch(void* const* d_in, const int* in_sizes, int n_in,
                              void* d_out, int out_size) {
    const float* logits   = (const float*)d_in[0];
    const int*   rankings = (const int*)d_in[1];
    int n  = in_sizes[0];
    int nt = (n + TILE - 1) / TILE;          // 64 for N=8192
    int nblocks = nt * (nt + 1) / 2;         // 2080

    wrnl_kernel<<<nblocks, TILE>>>(logits, rankings, (float*)d_out, n, nt, nblocks);
}